// round 4
// baseline (speedup 1.0000x reference)
#include <cuda_runtime.h>
#include <cstdint>

// Fixed shapes: B=16, K=64, H=96, W=96
constexpr int B = 16;
constexpr int K = 64;
constexpr int H = 96;
constexpr int W = 96;
constexpr int IMG = H * W;                      // 9216
constexpr int NSTACK = B * K;                   // 1024
constexpr long long NBIG = (long long)B * K * H * W;
constexpr int KP_ELEMS = B * 3 * K * 2;         // 6144
constexpr int ZETA_ELEMS = B * K;               // 1024

constexpr int THREADS = 256;                    // 8 warps
constexpr int CH_ROWS  = 32;                    // chunk = 32 rows
constexpr int CH_ELEMS = CH_ROWS * W;           // 3072 floats
constexpr int CH_BYTES = CH_ELEMS * 4;          // 12288 B
constexpr int CH_V4    = CH_ELEMS / 4;          // 768 float4
constexpr int CH_ITERS = CH_V4 / THREADS;       // 3
constexpr int CHUNKS_PER_IMG = H / CH_ROWS;     // 3
constexpr int IMGS_PER_BLK = 2;                 // Rk[stack], tf_Rk[stack]
constexpr int TOT_CHUNKS = CHUNKS_PER_IMG * IMGS_PER_BLK;  // 6

__device__ __forceinline__ float sigmoidf(float x) {
    return 1.0f / (1.0f + __expf(-x));
}

__global__ __launch_bounds__(THREADS)
void fused_decode_kernel(const float* __restrict__ Rk,
                         const float* __restrict__ tfRk,
                         float* __restrict__ Dk_out,
                         float* __restrict__ tfDk_out,
                         float* __restrict__ kp_out,
                         float* __restrict__ tfkp_out,
                         float* __restrict__ zeta_out,
                         float* __restrict__ tfzeta_out)
{
    __shared__ alignas(128) float buf[2][CH_ELEMS];   // 2 x 12 KB
    __shared__ alignas(8) unsigned long long mbar[2];
    __shared__ float sm0[8], smx[8], smy[8];

    const int stack = blockIdx.x;                 // 0..1023
    const int tid = threadIdx.x;
    const int lane = tid & 31;
    const int warp = tid >> 5;

    const uint32_t mbar_sa0 = (uint32_t)__cvta_generic_to_shared(&mbar[0]);
    const uint32_t mbar_sa1 = (uint32_t)__cvta_generic_to_shared(&mbar[1]);
    const uint32_t buf_sa0  = (uint32_t)__cvta_generic_to_shared(&buf[0][0]);
    const uint32_t buf_sa1  = (uint32_t)__cvta_generic_to_shared(&buf[1][0]);

    if (tid == 0) {
        asm volatile("mbarrier.init.shared.b64 [%0], %1;" :: "r"(mbar_sa0), "r"(1) : "memory");
        asm volatile("mbarrier.init.shared.b64 [%0], %1;" :: "r"(mbar_sa1), "r"(1) : "memory");
    }
    __syncthreads();

    // tid0: issue TMA for chunk t into buffer t&1
    auto issue = [&](int t) {
        const int img = t / CHUNKS_PER_IMG;       // 0 = Rk, 1 = tf_Rk
        const int ci  = t - img * CHUNKS_PER_IMG;
        const float* src = (img == 0 ? Rk : tfRk) + (size_t)stack * IMG + ci * CH_ELEMS;
        const uint32_t msa = (t & 1) ? mbar_sa1 : mbar_sa0;
        const uint32_t bsa = (t & 1) ? buf_sa1 : buf_sa0;
        asm volatile("mbarrier.arrive.expect_tx.shared.b64 _, [%0], %1;"
                     :: "r"(msa), "r"(CH_BYTES) : "memory");
        asm volatile("cp.async.bulk.shared::cta.global.mbarrier::complete_tx::bytes "
                     "[%0], [%1], %2, [%3];"
                     :: "r"(bsa), "l"(src), "r"(CH_BYTES), "r"(msa) : "memory");
    };

    if (tid == 0) issue(0);

    float s0 = 0.0f, sx = 0.0f, sy = 0.0f;

    for (int t = 0; t < TOT_CHUNKS; ++t) {
        if (t > 0) __syncthreads();   // buffer (t+1)&1 fully consumed; also protects sm arrays
        if (tid == 0 && t + 1 < TOT_CHUNKS) issue(t + 1);

        // wait for chunk t (buffer t&1, phase parity (t>>1)&1)
        {
            const uint32_t msa = (t & 1) ? mbar_sa1 : mbar_sa0;
            const uint32_t par = (uint32_t)((t >> 1) & 1);
            uint32_t done = 0;
            while (!done) {
                asm volatile(
                    "{\n\t.reg .pred p;\n\t"
                    "mbarrier.try_wait.parity.acquire.cta.shared::cta.b64 p, [%1], %2;\n\t"
                    "selp.b32 %0, 1, 0, p;\n\t}"
                    : "=r"(done) : "r"(msa), "r"(par) : "memory");
            }
        }

        const int img = t / CHUNKS_PER_IMG;
        const int ci  = t - img * CHUNKS_PER_IMG;
        float* __restrict__ Dimg = (img == 0 ? Dk_out : tfDk_out) + (size_t)stack * IMG;
        const float4* __restrict__ T4 = reinterpret_cast<const float4*>(buf[t & 1]);
        float4* __restrict__ D4 = reinterpret_cast<float4*>(Dimg) + ci * CH_V4;

#pragma unroll
        for (int it = 0; it < CH_ITERS; ++it) {
            const int v = tid + it * THREADS;     // float4 index within chunk [0,768)
            float4 r = T4[v];
            float4 d;
            d.x = sigmoidf(r.x);
            d.y = sigmoidf(r.y);
            d.z = sigmoidf(r.z);
            d.w = sigmoidf(r.w);
            D4[v] = d;

            const int e = v * 4;
            const int hl = e / W;                 // local row within chunk
            const int w = e - hl * W;
            const int h = hl + ci * CH_ROWS;      // global row
            const float rowsum = (d.x + d.y) + (d.z + d.w);
            s0 += rowsum;
            sy += rowsum * (float)h;
            sx += fmaf((float)w, rowsum, fmaf(3.0f, d.w, fmaf(2.0f, d.z, d.y)));
        }

        if (ci == CHUNKS_PER_IMG - 1) {
            // ---- finalize this image ----
#pragma unroll
            for (int o = 16; o > 0; o >>= 1) {
                s0 += __shfl_down_sync(0xffffffffu, s0, o);
                sx += __shfl_down_sync(0xffffffffu, sx, o);
                sy += __shfl_down_sync(0xffffffffu, sy, o);
            }
            if (lane == 0) { sm0[warp] = s0; smx[warp] = sx; smy[warp] = sy; }
            __syncthreads();

            if (tid == 0) {
                float z = 0.0f, fx = 0.0f, fy = 0.0f;
#pragma unroll
                for (int i = 0; i < 8; ++i) { z += sm0[i]; fx += smx[i]; fy += smy[i]; }

                const float kx = rintf(fx / z);   // jnp.round = round-half-even
                const float ky = rintf(fy / z);
                const int wi = (int)kx;
                const int hi = (int)ky;

                // d at rounded location: one global LDG (L2-hot), recompute sigmoid
                const float* Rimg = (img == 0 ? Rk : tfRk) + (size_t)stack * IMG;
                const float dloc = sigmoidf(__ldg(&Rimg[hi * W + wi]));

                const int b = stack / K;
                const int k = stack - b * K;
                float* kp_base   = (img == 0 ? kp_out : tfkp_out);
                float* zeta_base = (img == 0 ? zeta_out : tfzeta_out);

                float* kp  = kp_base + ((size_t)b * (3 * K) + k) * 2;
                float* kp1 = kp_base + ((size_t)b * (3 * K) + K + k) * 2;
                float* kp2 = kp_base + ((size_t)b * (3 * K) + 2 * K + k) * 2;
                kp[0]  = kx;
                kp[1]  = ky;
                kp1[0] = truncf(kx + kx * dloc);
                kp1[1] = truncf(ky + ky * dloc);
                kp2[0] = truncf(kx - kx * dloc);
                kp2[1] = truncf(ky - ky * dloc);

                zeta_base[stack] = z;
            }
            s0 = 0.0f; sx = 0.0f; sy = 0.0f;      // reset for next image
        }
    }
}

extern "C" void kernel_launch(void* const* d_in, const int* in_sizes, int n_in,
                              void* d_out, int out_size)
{
    const float* Rk   = (const float*)d_in[0];
    const float* tfRk = (const float*)d_in[1];

    float* out = (float*)d_out;
    float* Dk     = out;
    float* tfDk   = out + NBIG;
    float* kp     = out + 2 * NBIG;
    float* tfkp   = kp + KP_ELEMS;
    float* zeta   = tfkp + KP_ELEMS;
    float* tfzeta = zeta + ZETA_ELEMS;

    fused_decode_kernel<<<NSTACK, THREADS>>>(Rk, tfRk, Dk, tfDk, kp, tfkp, zeta, tfzeta);
}

// round 5
// speedup vs baseline: 1.0590x; 1.0590x over previous
#include <cuda_runtime.h>
#include <cstdint>

// Fixed shapes: B=16, K=64, H=96, W=96
constexpr int B = 16;
constexpr int K = 64;
constexpr int H = 96;
constexpr int W = 96;
constexpr int IMG = H * W;                      // 9216
constexpr int NSTACK = B * K;                   // 1024
constexpr long long NBIG = (long long)B * K * H * W;
constexpr int KP_ELEMS = B * 3 * K * 2;         // 6144
constexpr int ZETA_ELEMS = B * K;               // 1024

constexpr int THREADS = 256;                    // 8 warps
constexpr int NCHUNK = 3;                       // 3 chunks of 32 rows
constexpr int CH_ROWS  = H / NCHUNK;            // 32
constexpr int CH_ELEMS = CH_ROWS * W;           // 3072 floats
constexpr int CH_BYTES = CH_ELEMS * 4;          // 12288 B
constexpr int CH_V4    = CH_ELEMS / 4;          // 768 float4
constexpr int CH_ITERS = CH_V4 / THREADS;       // 3

__device__ __forceinline__ float sigmoidf(float x) {
    return 1.0f / (1.0f + __expf(-x));
}

__global__ __launch_bounds__(THREADS)
void fused_decode_kernel(const float* __restrict__ Rk,
                         const float* __restrict__ tfRk,
                         float* __restrict__ Dk_out,
                         float* __restrict__ tfDk_out,
                         float* __restrict__ kp_out,
                         float* __restrict__ tfkp_out,
                         float* __restrict__ zeta_out,
                         float* __restrict__ tfzeta_out)
{
    __shared__ alignas(128) float buf[NCHUNK][CH_ELEMS];   // 3 x 12 KB, written once each
    __shared__ alignas(8) unsigned long long mbar[NCHUNK];
    __shared__ float sm0[8], smx[8], smy[8];

    const int stack = blockIdx.x;                 // 0..1023
    const int which = blockIdx.y;                 // 0 = Rk, 1 = tf_Rk
    const int tid = threadIdx.x;
    const int lane = tid & 31;
    const int warp = tid >> 5;

    const float* __restrict__ R  = (which == 0 ? Rk : tfRk) + (size_t)stack * IMG;
    float* __restrict__ D        = (which == 0 ? Dk_out : tfDk_out) + (size_t)stack * IMG;
    float* __restrict__ kp_base  = (which == 0 ? kp_out : tfkp_out);
    float* __restrict__ zeta_base = (which == 0 ? zeta_out : tfzeta_out);

    if (tid < NCHUNK) {
        const uint32_t msa = (uint32_t)__cvta_generic_to_shared(&mbar[tid]);
        asm volatile("mbarrier.init.shared.b64 [%0], %1;" :: "r"(msa), "r"(1) : "memory");
    }
    __syncthreads();

    // ---- Fire ALL chunk TMAs upfront: full 36 KB in flight, compute starts
    //      as soon as the first 12 KB lands. Each chunk has its own mbarrier. ----
    if (tid == 0) {
#pragma unroll
        for (int c = 0; c < NCHUNK; ++c) {
            const uint32_t msa = (uint32_t)__cvta_generic_to_shared(&mbar[c]);
            const uint32_t bsa = (uint32_t)__cvta_generic_to_shared(&buf[c][0]);
            const float* src = R + c * CH_ELEMS;
            asm volatile("mbarrier.arrive.expect_tx.shared.b64 _, [%0], %1;"
                         :: "r"(msa), "r"(CH_BYTES) : "memory");
            asm volatile("cp.async.bulk.shared::cta.global.mbarrier::complete_tx::bytes "
                         "[%0], [%1], %2, [%3];"
                         :: "r"(bsa), "l"(src), "r"(CH_BYTES), "r"(msa) : "memory");
        }
    }

    float s0 = 0.0f, sx = 0.0f, sy = 0.0f;

#pragma unroll
    for (int c = 0; c < NCHUNK; ++c) {
        // wait chunk c (phase 0; each mbar used exactly once)
        {
            const uint32_t msa = (uint32_t)__cvta_generic_to_shared(&mbar[c]);
            uint32_t done = 0;
            while (!done) {
                asm volatile(
                    "{\n\t.reg .pred p;\n\t"
                    "mbarrier.try_wait.parity.acquire.cta.shared::cta.b64 p, [%1], %2;\n\t"
                    "selp.b32 %0, 1, 0, p;\n\t}"
                    : "=r"(done) : "r"(msa), "r"(0u) : "memory");
            }
        }

        const float4* __restrict__ T4 = reinterpret_cast<const float4*>(&buf[c][0]);
        float4* __restrict__ D4 = reinterpret_cast<float4*>(D) + c * CH_V4;

#pragma unroll
        for (int it = 0; it < CH_ITERS; ++it) {
            const int v = tid + it * THREADS;     // float4 index within chunk [0,768)
            float4 r = T4[v];
            float4 d;
            d.x = sigmoidf(r.x);
            d.y = sigmoidf(r.y);
            d.z = sigmoidf(r.z);
            d.w = sigmoidf(r.w);
            D4[v] = d;

            const int e = v * 4;
            const int hl = e / W;                 // local row within chunk
            const int w = e - hl * W;
            const int h = hl + c * CH_ROWS;       // global row
            const float rowsum = (d.x + d.y) + (d.z + d.w);
            s0 += rowsum;
            sy += rowsum * (float)h;
            sx += fmaf((float)w, rowsum, fmaf(3.0f, d.w, fmaf(2.0f, d.z, d.y)));
        }
    }

    // ---- block reduction ----
#pragma unroll
    for (int o = 16; o > 0; o >>= 1) {
        s0 += __shfl_down_sync(0xffffffffu, s0, o);
        sx += __shfl_down_sync(0xffffffffu, sx, o);
        sy += __shfl_down_sync(0xffffffffu, sy, o);
    }
    if (lane == 0) { sm0[warp] = s0; smx[warp] = sx; smy[warp] = sy; }
    __syncthreads();

    if (tid == 0) {
        float z = 0.0f, fx = 0.0f, fy = 0.0f;
#pragma unroll
        for (int i = 0; i < 8; ++i) { z += sm0[i]; fx += smx[i]; fy += smy[i]; }

        const float kx = rintf(fx / z);           // jnp.round = round-half-even
        const float ky = rintf(fy / z);
        const int wi = (int)kx;
        const int hi = (int)ky;

        // d at rounded location: buffers are never recycled -> read from smem
        const int ch = hi / CH_ROWS;
        const float dloc = sigmoidf(buf[ch][(hi - ch * CH_ROWS) * W + wi]);

        const int b = stack / K;
        const int k = stack - b * K;

        float* kp  = kp_base + ((size_t)b * (3 * K) + k) * 2;
        float* kp1 = kp_base + ((size_t)b * (3 * K) + K + k) * 2;
        float* kp2 = kp_base + ((size_t)b * (3 * K) + 2 * K + k) * 2;
        kp[0]  = kx;
        kp[1]  = ky;
        kp1[0] = truncf(kx + kx * dloc);
        kp1[1] = truncf(ky + ky * dloc);
        kp2[0] = truncf(kx - kx * dloc);
        kp2[1] = truncf(ky - ky * dloc);

        zeta_base[stack] = z;
    }
}

extern "C" void kernel_launch(void* const* d_in, const int* in_sizes, int n_in,
                              void* d_out, int out_size)
{
    const float* Rk   = (const float*)d_in[0];
    const float* tfRk = (const float*)d_in[1];

    float* out = (float*)d_out;
    float* Dk     = out;
    float* tfDk   = out + NBIG;
    float* kp     = out + 2 * NBIG;
    float* tfkp   = kp + KP_ELEMS;
    float* zeta   = tfkp + KP_ELEMS;
    float* tfzeta = zeta + ZETA_ELEMS;

    dim3 grid(NSTACK, 2);
    fused_decode_kernel<<<grid, THREADS>>>(Rk, tfRk, Dk, tfDk, kp, tfkp, zeta, tfzeta);
}